// round 1
// baseline (speedup 1.0000x reference)
#include <cuda_runtime.h>
#include <math.h>
#include <stdint.h>

// ---------------- problem dims ----------------
#define D1 48
#define H1 40
#define W1 48
#define V1 (D1*H1*W1)      // 92160
#define D2 96
#define H2 80
#define W2 96
#define V2 (D2*H2*W2)      // 737280

// ---------------- scratch arena (static: no runtime allocation) ----------------
// fl1 x_in layout (channels, each V1 floats):
//   [0..124] cv1, [125..156] feature_y, [157..188] warped_x, [189..220] ctx, [221..223] disp,
//   [224..287] out0, [288..335] out1, [336..367] out2           -> 368 channels
// fl2 x_in layout (channels, each V2 floats):
//   [0..26] cv2, [27..42] feature_y_up, [43..58] warped_x_up, [59..74] up_context,
//   [75..77] disp_up2, [78..109] out0                            -> 110 channels
constexpr size_t N_XIN1  = 368ull * V1;
constexpr size_t N_XIN2  = 110ull * V2;
constexpr size_t N_CTX   = 16ull  * V1;
constexpr size_t N_VEL   = 3ull   * V1;
constexpr size_t N_VELUP = 3ull   * V2;
constexpr size_t N_XOUT2 = 16ull  * V2;
constexpr size_t N_VELUP2= 3ull   * V2;
constexpr size_t N_WN1   = 32ull  * V1;
constexpr size_t N_TN1   = 32ull  * V1;
constexpr size_t N_WN2   = 16ull  * V2;
constexpr size_t N_TN2   = 16ull  * V2;

constexpr size_t O_XIN1   = 0;
constexpr size_t O_XIN2   = O_XIN1   + N_XIN1;
constexpr size_t O_CTX    = O_XIN2   + N_XIN2;
constexpr size_t O_VEL    = O_CTX    + N_CTX;
constexpr size_t O_VELUP  = O_VEL    + N_VEL;
constexpr size_t O_XOUT2  = O_VELUP  + N_VELUP;
constexpr size_t O_VELUP2 = O_XOUT2  + N_XOUT2;
constexpr size_t O_WN1    = O_VELUP2 + N_VELUP2;
constexpr size_t O_TN1    = O_WN1    + N_WN1;
constexpr size_t O_WN2    = O_TN1    + N_TN1;
constexpr size_t O_TN2    = O_WN2    + N_WN2;
constexpr size_t ARENA_TOTAL = O_TN2 + N_TN2;

__device__ float  g_arena[ARENA_TOTAL];
__device__ double g_red[4];   // sumA, sqA, sumB, sqB
__device__ float  g_ms[2];    // m, 1/s

// ---------------- small kernels ----------------
__global__ void k_zero_red() {
    if (threadIdx.x < 4) g_red[threadIdx.x] = 0.0;
}

__global__ void k_reduce(const float* __restrict__ x, int n, int slot) {
    __shared__ double ss[256];
    __shared__ double sq[256];
    double s = 0.0, q = 0.0;
    for (int i = blockIdx.x * blockDim.x + threadIdx.x; i < n; i += gridDim.x * blockDim.x) {
        double v = (double)x[i];
        s += v; q += v * v;
    }
    int tid = threadIdx.x;
    ss[tid] = s; sq[tid] = q;
    __syncthreads();
    for (int o = 128; o > 0; o >>= 1) {
        if (tid < o) { ss[tid] += ss[tid + o]; sq[tid] += sq[tid + o]; }
        __syncthreads();
    }
    if (tid == 0) {
        atomicAdd(&g_red[slot],     ss[0]);
        atomicAdd(&g_red[slot + 1], sq[0]);
    }
}

__global__ void k_finalize_ms(double n) {
    double ma = g_red[0] / n;
    double mb = g_red[2] / n;
    double va = (g_red[1] - g_red[0] * g_red[0] / n) / (n - 1.0);
    double vb = (g_red[3] - g_red[2] * g_red[2] / n) / (n - 1.0);
    double s  = 0.5 * (sqrt(va) + sqrt(vb));
    g_ms[0] = (float)(0.5 * (ma + mb));
    g_ms[1] = (float)(1.0 / s);
}

__global__ void k_normalize(const float* __restrict__ x, float* __restrict__ y, int n) {
    float m = g_ms[0], is = g_ms[1];
    for (int i = blockIdx.x * blockDim.x + threadIdx.x; i < n; i += gridDim.x * blockDim.x)
        y[i] = (x[i] - m) * is;
}

// ---------------- warp (STN trilinear grid sample, zero padding) ----------------
__global__ void k_warp(const float* __restrict__ vol, const float* __restrict__ flow,
                       float* __restrict__ out, int C, int D, int H, int W, int addFlow) {
    size_t V = (size_t)D * H * W;
    int HW = H * W;
    for (size_t p = blockIdx.x * (size_t)blockDim.x + threadIdx.x; p < V;
         p += (size_t)gridDim.x * blockDim.x) {
        int z = (int)(p / HW); int r = (int)(p % HW); int y = r / W; int x = r % W;
        float cz = z + flow[p];
        float cy = y + flow[V + p];
        float cx = x + flow[2 * V + p];
        float fz0 = floorf(cz), fy0 = floorf(cy), fx0 = floorf(cx);
        int z0 = (int)fz0, y0 = (int)fy0, x0 = (int)fx0;
        float fz = cz - fz0, fy = cy - fy0, fx = cx - fx0;
        float wz[2] = {1.f - fz, fz}, wy[2] = {1.f - fy, fy}, wx[2] = {1.f - fx, fx};
        int   idx[8]; float w8[8];
        #pragma unroll
        for (int dz = 0; dz < 2; dz++)
        #pragma unroll
        for (int dy = 0; dy < 2; dy++)
        #pragma unroll
        for (int dx = 0; dx < 2; dx++) {
            int zi = z0 + dz, yi = y0 + dy, xi = x0 + dx;
            bool valid = (zi >= 0 && zi < D && yi >= 0 && yi < H && xi >= 0 && xi < W);
            int zc = min(max(zi, 0), D - 1);
            int yc = min(max(yi, 0), H - 1);
            int xc = min(max(xi, 0), W - 1);
            int k = dz * 4 + dy * 2 + dx;
            idx[k] = zc * HW + yc * W + xc;
            w8[k]  = valid ? wz[dz] * wy[dy] * wx[dx] : 0.f;
        }
        for (int c = 0; c < C; c++) {
            const float* vc = vol + (size_t)c * V;
            float a = 0.f;
            #pragma unroll
            for (int k = 0; k < 8; k++) a += w8[k] * vc[idx[k]];
            out[(size_t)c * V + p] = a + (addFlow ? flow[(size_t)c * V + p] : 0.f);
        }
    }
}

// final: vf = (warp(disp2, vel2) + vel2 - disp_up) / (1 - t)
__global__ void k_final(const float* __restrict__ disp2, const float* __restrict__ vel2,
                        const float* __restrict__ dispup, const float* __restrict__ tptr,
                        float* __restrict__ out) {
    const int D = D2, H = H2, W = W2;
    const size_t V = (size_t)V2;
    const int HW = H * W;
    float inv = 1.f / (1.f - tptr[0]);
    for (size_t p = blockIdx.x * (size_t)blockDim.x + threadIdx.x; p < V;
         p += (size_t)gridDim.x * blockDim.x) {
        int z = (int)(p / HW); int r = (int)(p % HW); int y = r / W; int x = r % W;
        float cz = z + vel2[p];
        float cy = y + vel2[V + p];
        float cx = x + vel2[2 * V + p];
        float fz0 = floorf(cz), fy0 = floorf(cy), fx0 = floorf(cx);
        int z0 = (int)fz0, y0 = (int)fy0, x0 = (int)fx0;
        float fz = cz - fz0, fy = cy - fy0, fx = cx - fx0;
        float wz[2] = {1.f - fz, fz}, wy[2] = {1.f - fy, fy}, wx[2] = {1.f - fx, fx};
        int idx[8]; float w8[8];
        #pragma unroll
        for (int dz = 0; dz < 2; dz++)
        #pragma unroll
        for (int dy = 0; dy < 2; dy++)
        #pragma unroll
        for (int dx = 0; dx < 2; dx++) {
            int zi = z0 + dz, yi = y0 + dy, xi = x0 + dx;
            bool valid = (zi >= 0 && zi < D && yi >= 0 && yi < H && xi >= 0 && xi < W);
            int zc = min(max(zi, 0), D - 1);
            int yc = min(max(yi, 0), H - 1);
            int xc = min(max(xi, 0), W - 1);
            int k = dz * 4 + dy * 2 + dx;
            idx[k] = zc * HW + yc * W + xc;
            w8[k]  = valid ? wz[dz] * wy[dy] * wx[dx] : 0.f;
        }
        #pragma unroll
        for (int c = 0; c < 3; c++) {
            const float* vc = disp2 + (size_t)c * V;
            float a = 0.f;
            #pragma unroll
            for (int k = 0; k < 8; k++) a += w8[k] * vc[idx[k]];
            out[(size_t)c * V + p] = (a + vel2[(size_t)c * V + p] - dispup[(size_t)c * V + p]) * inv;
        }
    }
}

// ---------------- jax.image.resize (trilinear, antialias) ----------------
// downsample by 2: taps {2o-1..2o+2}, raw weights {1,3,3,1}, invalid dropped, renormalized
__device__ __forceinline__ int taps_down(int o, int n, int* ti, float* tw) {
    const float raw[4] = {1.f, 3.f, 3.f, 1.f};
    int m = 0; float tot = 0.f;
    #pragma unroll
    for (int k = 0; k < 4; k++) {
        int t = 2 * o - 1 + k;
        if (t >= 0 && t < n) { ti[m] = t; tw[m] = raw[k]; tot += raw[k]; m++; }
    }
    float inv = 1.f / tot;
    for (int i = 0; i < m; i++) tw[i] *= inv;
    return m;
}

__global__ void k_resize_down(const float* __restrict__ in, float* __restrict__ out, float scale) {
    // in [3, D2,H2,W2] -> out [3, D1,H1,W1]
    int n = 3 * V1;
    for (int idx = blockIdx.x * blockDim.x + threadIdx.x; idx < n; idx += gridDim.x * blockDim.x) {
        int c = idx / V1; int p = idx % V1;
        int z = p / (H1 * W1); int r = p % (H1 * W1); int y = r / W1; int x = r % W1;
        int zi[4], yi[4], xi[4]; float zw[4], yw[4], xw[4];
        int mz = taps_down(z, D2, zi, zw);
        int my = taps_down(y, H2, yi, yw);
        int mx = taps_down(x, W2, xi, xw);
        const float* ic = in + (size_t)c * V2;
        float a = 0.f;
        for (int iz = 0; iz < mz; iz++)
            for (int iy = 0; iy < my; iy++) {
                float wzy = zw[iz] * yw[iy];
                const float* row = ic + (size_t)zi[iz] * (H2 * W2) + yi[iy] * W2;
                for (int ix = 0; ix < mx; ix++) a += wzy * xw[ix] * row[xi[ix]];
            }
        out[idx] = a * scale;
    }
}

// upsample by 2: even 2j -> {j-1:0.25, j:0.75} (edge: all on j); odd 2j+1 -> {j:0.75, j+1:0.25}
__device__ __forceinline__ void taps_up(int o, int n, int& i0, int& i1, float& w0, float& w1) {
    int j = o >> 1;
    if ((o & 1) == 0) {
        if (j == 0) { i0 = 0; i1 = 0; w0 = 1.f; w1 = 0.f; }
        else        { i0 = j - 1; i1 = j; w0 = 0.25f; w1 = 0.75f; }
    } else {
        if (j + 1 >= n) { i0 = j; i1 = j; w0 = 1.f; w1 = 0.f; }
        else            { i0 = j; i1 = j + 1; w0 = 0.75f; w1 = 0.25f; }
    }
}

__global__ void k_resize_up(const float* __restrict__ in, float* __restrict__ out, int C, float scale) {
    // in [C, D1,H1,W1] -> out [C, D2,H2,W2]
    size_t n = (size_t)C * V2;
    for (size_t idx = blockIdx.x * (size_t)blockDim.x + threadIdx.x; idx < n;
         idx += (size_t)gridDim.x * blockDim.x) {
        int c = (int)(idx / V2); int p = (int)(idx % V2);
        int z = p / (H2 * W2); int r = p % (H2 * W2); int y = r / W2; int x = r % W2;
        int z0, z1, y0, y1, x0, x1; float wz0, wz1, wy0, wy1, wx0, wx1;
        taps_up(z, D1, z0, z1, wz0, wz1);
        taps_up(y, H1, y0, y1, wy0, wy1);
        taps_up(x, W1, x0, x1, wx0, wx1);
        const float* ic = in + (size_t)c * V1;
        const int HW = H1 * W1;
        float a =
            wz0 * (wy0 * (wx0 * ic[z0*HW + y0*W1 + x0] + wx1 * ic[z0*HW + y0*W1 + x1]) +
                   wy1 * (wx0 * ic[z0*HW + y1*W1 + x0] + wx1 * ic[z0*HW + y1*W1 + x1])) +
            wz1 * (wy0 * (wx0 * ic[z1*HW + y0*W1 + x0] + wx1 * ic[z1*HW + y0*W1 + x1]) +
                   wy1 * (wx0 * ic[z1*HW + y1*W1 + x0] + wx1 * ic[z1*HW + y1*W1 + x1]));
        out[idx] = a * scale;
    }
}

// ---------------- cost volume (+ leaky 0.05) ----------------
// out channel (i*N+j)*N+k at voxel p: mean_c f1[c,p] * f2[c, p + (i-MD, j-MD, k-MD)], zero OOB
template <int MD>
__global__ void k_costvol(const float* __restrict__ f1, const float* __restrict__ f2,
                          float* __restrict__ out, int C, int D, int H, int W) {
    const int N = 2 * MD + 1;
    size_t V = (size_t)D * H * W;
    const int HW = H * W;
    int i = blockIdx.y;     // z-offset index 0..N-1
    float invC = 1.f / (float)C;
    for (size_t p = blockIdx.x * (size_t)blockDim.x + threadIdx.x; p < V;
         p += (size_t)gridDim.x * blockDim.x) {
        int z = (int)(p / HW); int r = (int)(p % HW); int y = r / W; int x = r % W;
        float acc[N * N];
        #pragma unroll
        for (int q = 0; q < N * N; q++) acc[q] = 0.f;
        int zq = z + i - MD;
        if (zq >= 0 && zq < D) {
            for (int c = 0; c < C; c++) {
                float tv = f1[(size_t)c * V + p];
                const float* f2c = f2 + (size_t)c * V + (size_t)zq * HW;
                #pragma unroll
                for (int j = 0; j < N; j++) {
                    int yq = y + j - MD;
                    if (yq < 0 || yq >= H) continue;
                    #pragma unroll
                    for (int k = 0; k < N; k++) {
                        int xq = x + k - MD;
                        if (xq < 0 || xq >= W) continue;
                        acc[j * N + k] += tv * f2c[yq * W + xq];
                    }
                }
            }
        }
        #pragma unroll
        for (int j = 0; j < N; j++)
        #pragma unroll
        for (int k = 0; k < N; k++) {
            float v = acc[j * N + k] * invC;
            v = (v >= 0.f) ? v : 0.05f * v;
            out[(size_t)((i * N + j) * N + k) * V + p] = v;
        }
    }
}

// ---------------- conv3d (3x3x3, SAME), register-blocked direct conv ----------------
// Block: TX x TY threads, each thread computes VZ z-positions x 16 output channels.
template <int TX, int TY, int VZ>
__global__ void __launch_bounds__(TX * TY)
k_conv3d(const float* __restrict__ in, const float* __restrict__ wg,
         const float* __restrict__ bias, float* __restrict__ out,
         int Cin, int Cout, int D, int H, int W, int zTiles, float slope) {
    const int NT = TX * TY;
    const int IW = TX + 2, IH = TY + 2, IZ = VZ + 2;
    const int ITILE = IZ * IH * IW;
    __shared__ float s_in[ITILE];
    __shared__ __align__(16) float s_w[27 * 16];

    const int tx = threadIdx.x, ty = threadIdx.y;
    const int tid = ty * TX + tx;
    const int x0 = blockIdx.x * TX, y0 = blockIdx.y * TY;
    const int zt = blockIdx.z % zTiles, ct = blockIdx.z / zTiles;
    const int z0 = zt * VZ;
    const int coutBase = ct * 16;
    const int HW = H * W;
    const size_t V = (size_t)D * HW;

    float acc[16 * VZ];
    #pragma unroll
    for (int q = 0; q < 16 * VZ; q++) acc[q] = 0.f;

    for (int ci = 0; ci < Cin; ci++) {
        const float* inc = in + (size_t)ci * V;
        // stage input tile (zero-padded halo)
        for (int l = tid; l < ITILE; l += NT) {
            int zz = l / (IH * IW); int r = l % (IH * IW); int yy = r / IW; int xx = r % IW;
            int gz = z0 - 1 + zz, gy = y0 - 1 + yy, gx = x0 - 1 + xx;
            float v = 0.f;
            if (gz >= 0 && gz < D && gy >= 0 && gy < H && gx >= 0 && gx < W)
                v = inc[(size_t)gz * HW + gy * W + gx];
            s_in[l] = v;
        }
        // stage weights [tap][co] for 16-channel cout tile
        for (int l = tid; l < 432; l += NT) {
            int tap = l >> 4, co = l & 15;
            int cog = coutBase + co;
            s_w[l] = (cog < Cout) ? wg[((size_t)cog * Cin + ci) * 27 + tap] : 0.f;
        }
        __syncthreads();

        #pragma unroll
        for (int kz = 0; kz < 3; kz++)
        #pragma unroll
        for (int ky = 0; ky < 3; ky++)
        #pragma unroll
        for (int kx = 0; kx < 3; kx++) {
            const int tap = kz * 9 + ky * 3 + kx;
            float iv[VZ];
            #pragma unroll
            for (int vz = 0; vz < VZ; vz++)
                iv[vz] = s_in[(vz + kz) * IH * IW + (ty + ky) * IW + (tx + kx)];
            #pragma unroll
            for (int c4 = 0; c4 < 4; c4++) {
                float4 w4 = *reinterpret_cast<const float4*>(s_w + tap * 16 + c4 * 4);
                #pragma unroll
                for (int vz = 0; vz < VZ; vz++) {
                    acc[(c4 * 4 + 0) * VZ + vz] += w4.x * iv[vz];
                    acc[(c4 * 4 + 1) * VZ + vz] += w4.y * iv[vz];
                    acc[(c4 * 4 + 2) * VZ + vz] += w4.z * iv[vz];
                    acc[(c4 * 4 + 3) * VZ + vz] += w4.w * iv[vz];
                }
            }
        }
        __syncthreads();
    }

    const int gx = x0 + tx, gy = y0 + ty;
    if (gx < W && gy < H) {
        #pragma unroll
        for (int co = 0; co < 16; co++) {
            int cog = coutBase + co;
            if (cog < Cout) {
                float b = bias[cog];
                #pragma unroll
                for (int vz = 0; vz < VZ; vz++) {
                    int gz = z0 + vz;
                    if (gz < D) {
                        float v = acc[co * VZ + vz] + b;
                        v = (v >= 0.f) ? v : v * slope;
                        out[(size_t)cog * V + (size_t)gz * HW + (size_t)gy * W + gx] = v;
                    }
                }
            }
        }
    }
}

// ---------------- host-side launch helpers ----------------
static void launch_conv_coarse(const float* in, const float* w, const float* b, float* out,
                               int Cin, int Cout, float slope) {
    dim3 blk(16, 4);
    int zT = D1 / 4;                         // 12
    dim3 grd(W1 / 16, H1 / 4, zT * ((Cout + 15) / 16));
    k_conv3d<16, 4, 4><<<grd, blk>>>(in, w, b, out, Cin, Cout, D1, H1, W1, zT, slope);
}

static void launch_conv_fine(const float* in, const float* w, const float* b, float* out,
                             int Cin, int Cout, float slope) {
    dim3 blk(32, 4);
    int zT = D2 / 4;                         // 24
    dim3 grd(W2 / 32, H2 / 4, zT * ((Cout + 15) / 16));
    k_conv3d<32, 4, 4><<<grd, blk>>>(in, w, b, out, Cin, Cout, D2, H2, W2, zT, slope);
}

extern "C" void kernel_launch(void* const* d_in, const int* in_sizes, int n_in,
                              void* d_out, int out_size) {
    const float* t_ptr  = (const float*)d_in[0];
    const float* dispup = (const float*)d_in[1];
    const float* fx     = (const float*)d_in[2];
    const float* fy     = (const float*)d_in[3];
    const float* fxu    = (const float*)d_in[4];
    const float* fyu    = (const float*)d_in[5];
    const float* ctx    = (const float*)d_in[6];
    const float* w1_[5] = {(const float*)d_in[7],  (const float*)d_in[9],
                           (const float*)d_in[11], (const float*)d_in[13],
                           (const float*)d_in[15]};
    const float* b1_[5] = {(const float*)d_in[8],  (const float*)d_in[10],
                           (const float*)d_in[12], (const float*)d_in[14],
                           (const float*)d_in[16]};
    const float* w2_[3] = {(const float*)d_in[17], (const float*)d_in[19],
                           (const float*)d_in[21]};
    const float* b2_[3] = {(const float*)d_in[18], (const float*)d_in[20],
                           (const float*)d_in[22]};

    float* A = nullptr;
    cudaGetSymbolAddress((void**)&A, g_arena);

    float* xin1   = A + O_XIN1;
    float* xin2   = A + O_XIN2;
    float* ctx16  = A + O_CTX;
    float* vel    = A + O_VEL;
    float* velup  = A + O_VELUP;
    float* xout2  = A + O_XOUT2;
    float* velup2 = A + O_VELUP2;
    float* wn1    = A + O_WN1;
    float* tn1    = A + O_TN1;
    float* wn2    = A + O_WN2;
    float* tn2    = A + O_TN2;

    float* cv1    = xin1;
    float* fyc    = xin1 + 125ull * V1;
    float* wx     = xin1 + 157ull * V1;
    float* ctxc   = xin1 + 189ull * V1;
    float* disp   = xin1 + 221ull * V1;

    float* cv2    = xin2;
    float* fyuc   = xin2 + 27ull * V2;
    float* wxu    = xin2 + 43ull * V2;
    float* upctx  = xin2 + 59ull * V2;
    float* disp2  = xin2 + 75ull * V2;

    float* outf = (float*)d_out;

    const int TPB = 256;
    const int GB1 = (V1 + TPB - 1) / TPB;          // 360
    const int GB2 = (V2 + TPB - 1) / TPB;          // 2880

    // zero entire output (vf + five zero tensors)
    cudaMemsetAsync(d_out, 0, (size_t)out_size * sizeof(float), 0);

    // ---- coarse stage ----
    // disp = resize(disp_up, 0.5) * 0.5
    k_resize_down<<<(3 * V1 + TPB - 1) / TPB, TPB>>>(dispup, disp, 0.5f);
    // warped_x = warp(feature_x, disp)
    k_warp<<<GB1, TPB>>>(fx, disp, wx, 32, D1, H1, W1, 0);
    // concat copies
    cudaMemcpyAsync(fyc,  fy,  32ull * V1 * sizeof(float), cudaMemcpyDeviceToDevice, 0);
    cudaMemcpyAsync(ctxc, ctx, 32ull * V1 * sizeof(float), cudaMemcpyDeviceToDevice, 0);
    // normalize pair (warped_x, feature_y)
    k_zero_red<<<1, 4>>>();
    k_reduce<<<512, 256>>>(wx, 32 * V1, 0);
    k_reduce<<<512, 256>>>(fy, 32 * V1, 2);
    k_finalize_ms<<<1, 1>>>((double)(32 * V1));
    k_normalize<<<(32 * V1 + TPB - 1) / TPB, TPB>>>(wx, wn1, 32 * V1);
    k_normalize<<<(32 * V1 + TPB - 1) / TPB, TPB>>>(fy, tn1, 32 * V1);
    // cv1 = leaky(cost_volume(tn1, wn1, md=2), 0.05)  -> 125 channels
    k_costvol<2><<<dim3(GB1, 5), TPB>>>(tn1, wn1, cv1, 32, D1, H1, W1);
    // fl1 dense block
    launch_conv_coarse(xin1, w1_[0], b1_[0], xin1 + 224ull * V1, 224, 64, 0.02f);
    launch_conv_coarse(xin1, w1_[1], b1_[1], xin1 + 288ull * V1, 288, 48, 0.02f);
    launch_conv_coarse(xin1, w1_[2], b1_[2], xin1 + 336ull * V1, 336, 32, 0.02f);
    launch_conv_coarse(xin1, w1_[3], b1_[3], ctx16,              368, 16, 0.02f);
    launch_conv_coarse(ctx16, w1_[4], b1_[4], vel,                16,  3, 1.0f);

    // ---- upsample + fine stage ----
    k_resize_up<<<GB2 * 2, TPB>>>(ctx16, upctx, 16, 1.0f);
    k_resize_up<<<GB2, TPB>>>(vel, velup, 3, 2.0f);
    // disp_up2 = warp(disp_up, velocity_up) + velocity_up
    k_warp<<<GB2, TPB>>>(dispup, velup, disp2, 3, D2, H2, W2, 1);
    // warped_x_up = warp(feature_x_up, disp_up2)
    k_warp<<<GB2, TPB>>>(fxu, disp2, wxu, 16, D2, H2, W2, 0);
    cudaMemcpyAsync(fyuc, fyu, 16ull * V2 * sizeof(float), cudaMemcpyDeviceToDevice, 0);
    // normalize pair (warped_x_up, feature_y_up)
    k_zero_red<<<1, 4>>>();
    k_reduce<<<1024, 256>>>(wxu, 16 * V2, 0);
    k_reduce<<<1024, 256>>>(fyu, 16 * V2, 2);
    k_finalize_ms<<<1, 1>>>((double)(16 * V2));
    k_normalize<<<(16 * V2 + TPB - 1) / TPB, TPB>>>(wxu, wn2, 16 * V2);
    k_normalize<<<(16 * V2 + TPB - 1) / TPB, TPB>>>(fyu, tn2, 16 * V2);
    // cv2 = leaky(cost_volume(tn2, wn2, md=1), 0.05) -> 27 channels
    k_costvol<1><<<dim3(GB2, 3), TPB>>>(tn2, wn2, cv2, 16, D2, H2, W2);
    // fl2 dense block
    launch_conv_fine(xin2, w2_[0], b2_[0], xin2 + 78ull * V2, 78, 32, 0.02f);
    launch_conv_fine(xin2, w2_[1], b2_[1], xout2,            110, 16, 0.02f);
    launch_conv_fine(xout2, w2_[2], b2_[2], velup2,           16,  3, 1.0f);

    // vf = (warp(disp_up2, velocity_up2) + velocity_up2 - disp_up) / (1 - t)
    k_final<<<GB2, TPB>>>(disp2, velup2, dispup, t_ptr, outf);
}

// round 2
// speedup vs baseline: 1.1585x; 1.1585x over previous
#include <cuda_runtime.h>
#include <math.h>
#include <stdint.h>

// ---------------- problem dims ----------------
#define D1 48
#define H1 40
#define W1 48
#define V1 (D1*H1*W1)      // 92160
#define D2 96
#define H2 80
#define W2 96
#define V2 (D2*H2*W2)      // 737280

// ---------------- scratch arena (static: no runtime allocation) ----------------
constexpr size_t N_XIN1  = 368ull * V1;
constexpr size_t N_XIN2  = 110ull * V2;
constexpr size_t N_CTX   = 16ull  * V1;
constexpr size_t N_VEL   = 3ull   * V1;
constexpr size_t N_VELUP = 3ull   * V2;
constexpr size_t N_XOUT2 = 16ull  * V2;
constexpr size_t N_VELUP2= 3ull   * V2;
constexpr size_t N_WN1   = 32ull  * V1;
constexpr size_t N_TN1   = 32ull  * V1;
constexpr size_t N_WN2   = 16ull  * V2;
constexpr size_t N_TN2   = 16ull  * V2;

constexpr size_t O_XIN1   = 0;
constexpr size_t O_XIN2   = O_XIN1   + N_XIN1;
constexpr size_t O_CTX    = O_XIN2   + N_XIN2;
constexpr size_t O_VEL    = O_CTX    + N_CTX;
constexpr size_t O_VELUP  = O_VEL    + N_VEL;
constexpr size_t O_XOUT2  = O_VELUP  + N_VELUP;
constexpr size_t O_VELUP2 = O_XOUT2  + N_XOUT2;
constexpr size_t O_WN1    = O_VELUP2 + N_VELUP2;
constexpr size_t O_TN1    = O_WN1    + N_WN1;
constexpr size_t O_WN2    = O_TN1    + N_TN1;
constexpr size_t O_TN2    = O_WN2    + N_WN2;
constexpr size_t ARENA_TOTAL = O_TN2 + N_TN2;

__device__ float  g_arena[ARENA_TOTAL];
__device__ double g_red[4];   // sumA, sqA, sumB, sqB
__device__ float  g_ms[2];    // m, 1/s

// ---------------- f32x2 helpers ----------------
__device__ __forceinline__ unsigned long long dup_f32x2(float v) {
    unsigned long long r;
    asm("mov.b64 %0, {%1, %1};" : "=l"(r) : "f"(v));
    return r;
}
__device__ __forceinline__ void fma_f32x2(unsigned long long& d,
                                          unsigned long long a,
                                          unsigned long long b) {
    asm("fma.rn.f32x2 %0, %1, %2, %0;" : "+l"(d) : "l"(a), "l"(b));
}
__device__ __forceinline__ void unpack_f32x2(unsigned long long v, float& lo, float& hi) {
    asm("mov.b64 {%0, %1}, %2;" : "=f"(lo), "=f"(hi) : "l"(v));
}

// ---------------- small kernels ----------------
__global__ void k_zero_red() {
    if (threadIdx.x < 4) g_red[threadIdx.x] = 0.0;
}

__global__ void k_reduce(const float* __restrict__ x, int n, int slot) {
    __shared__ double ss[256];
    __shared__ double sq[256];
    double s = 0.0, q = 0.0;
    for (int i = blockIdx.x * blockDim.x + threadIdx.x; i < n; i += gridDim.x * blockDim.x) {
        double v = (double)x[i];
        s += v; q += v * v;
    }
    int tid = threadIdx.x;
    ss[tid] = s; sq[tid] = q;
    __syncthreads();
    for (int o = 128; o > 0; o >>= 1) {
        if (tid < o) { ss[tid] += ss[tid + o]; sq[tid] += sq[tid + o]; }
        __syncthreads();
    }
    if (tid == 0) {
        atomicAdd(&g_red[slot],     ss[0]);
        atomicAdd(&g_red[slot + 1], sq[0]);
    }
}

__global__ void k_finalize_ms(double n) {
    double ma = g_red[0] / n;
    double mb = g_red[2] / n;
    double va = (g_red[1] - g_red[0] * g_red[0] / n) / (n - 1.0);
    double vb = (g_red[3] - g_red[2] * g_red[2] / n) / (n - 1.0);
    double s  = 0.5 * (sqrt(va) + sqrt(vb));
    g_ms[0] = (float)(0.5 * (ma + mb));
    g_ms[1] = (float)(1.0 / s);
}

__global__ void k_normalize(const float* __restrict__ x, float* __restrict__ y, int n) {
    float m = g_ms[0], is = g_ms[1];
    for (int i = blockIdx.x * blockDim.x + threadIdx.x; i < n; i += gridDim.x * blockDim.x)
        y[i] = (x[i] - m) * is;
}

// ---------------- warp (STN trilinear grid sample, zero padding) ----------------
__global__ void k_warp(const float* __restrict__ vol, const float* __restrict__ flow,
                       float* __restrict__ out, int C, int D, int H, int W, int addFlow) {
    size_t V = (size_t)D * H * W;
    int HW = H * W;
    for (size_t p = blockIdx.x * (size_t)blockDim.x + threadIdx.x; p < V;
         p += (size_t)gridDim.x * blockDim.x) {
        int z = (int)(p / HW); int r = (int)(p % HW); int y = r / W; int x = r % W;
        float cz = z + flow[p];
        float cy = y + flow[V + p];
        float cx = x + flow[2 * V + p];
        float fz0 = floorf(cz), fy0 = floorf(cy), fx0 = floorf(cx);
        int z0 = (int)fz0, y0 = (int)fy0, x0 = (int)fx0;
        float fz = cz - fz0, fy = cy - fy0, fx = cx - fx0;
        float wz[2] = {1.f - fz, fz}, wy[2] = {1.f - fy, fy}, wx[2] = {1.f - fx, fx};
        int   idx[8]; float w8[8];
        #pragma unroll
        for (int dz = 0; dz < 2; dz++)
        #pragma unroll
        for (int dy = 0; dy < 2; dy++)
        #pragma unroll
        for (int dx = 0; dx < 2; dx++) {
            int zi = z0 + dz, yi = y0 + dy, xi = x0 + dx;
            bool valid = (zi >= 0 && zi < D && yi >= 0 && yi < H && xi >= 0 && xi < W);
            int zc = min(max(zi, 0), D - 1);
            int yc = min(max(yi, 0), H - 1);
            int xc = min(max(xi, 0), W - 1);
            int k = dz * 4 + dy * 2 + dx;
            idx[k] = zc * HW + yc * W + xc;
            w8[k]  = valid ? wz[dz] * wy[dy] * wx[dx] : 0.f;
        }
        for (int c = 0; c < C; c++) {
            const float* vc = vol + (size_t)c * V;
            float a = 0.f;
            #pragma unroll
            for (int k = 0; k < 8; k++) a += w8[k] * vc[idx[k]];
            out[(size_t)c * V + p] = a + (addFlow ? flow[(size_t)c * V + p] : 0.f);
        }
    }
}

// final: vf = (warp(disp2, vel2) + vel2 - disp_up) / (1 - t)
__global__ void k_final(const float* __restrict__ disp2, const float* __restrict__ vel2,
                        const float* __restrict__ dispup, const float* __restrict__ tptr,
                        float* __restrict__ out) {
    const int D = D2, H = H2, W = W2;
    const size_t V = (size_t)V2;
    const int HW = H * W;
    float inv = 1.f / (1.f - tptr[0]);
    for (size_t p = blockIdx.x * (size_t)blockDim.x + threadIdx.x; p < V;
         p += (size_t)gridDim.x * blockDim.x) {
        int z = (int)(p / HW); int r = (int)(p % HW); int y = r / W; int x = r % W;
        float cz = z + vel2[p];
        float cy = y + vel2[V + p];
        float cx = x + vel2[2 * V + p];
        float fz0 = floorf(cz), fy0 = floorf(cy), fx0 = floorf(cx);
        int z0 = (int)fz0, y0 = (int)fy0, x0 = (int)fx0;
        float fz = cz - fz0, fy = cy - fy0, fx = cx - fx0;
        float wz[2] = {1.f - fz, fz}, wy[2] = {1.f - fy, fy}, wx[2] = {1.f - fx, fx};
        int idx[8]; float w8[8];
        #pragma unroll
        for (int dz = 0; dz < 2; dz++)
        #pragma unroll
        for (int dy = 0; dy < 2; dy++)
        #pragma unroll
        for (int dx = 0; dx < 2; dx++) {
            int zi = z0 + dz, yi = y0 + dy, xi = x0 + dx;
            bool valid = (zi >= 0 && zi < D && yi >= 0 && yi < H && xi >= 0 && xi < W);
            int zc = min(max(zi, 0), D - 1);
            int yc = min(max(yi, 0), H - 1);
            int xc = min(max(xi, 0), W - 1);
            int k = dz * 4 + dy * 2 + dx;
            idx[k] = zc * HW + yc * W + xc;
            w8[k]  = valid ? wz[dz] * wy[dy] * wx[dx] : 0.f;
        }
        #pragma unroll
        for (int c = 0; c < 3; c++) {
            const float* vc = disp2 + (size_t)c * V;
            float a = 0.f;
            #pragma unroll
            for (int k = 0; k < 8; k++) a += w8[k] * vc[idx[k]];
            out[(size_t)c * V + p] = (a + vel2[(size_t)c * V + p] - dispup[(size_t)c * V + p]) * inv;
        }
    }
}

// ---------------- jax.image.resize (trilinear, antialias) ----------------
__device__ __forceinline__ int taps_down(int o, int n, int* ti, float* tw) {
    const float raw[4] = {1.f, 3.f, 3.f, 1.f};
    int m = 0; float tot = 0.f;
    #pragma unroll
    for (int k = 0; k < 4; k++) {
        int t = 2 * o - 1 + k;
        if (t >= 0 && t < n) { ti[m] = t; tw[m] = raw[k]; tot += raw[k]; m++; }
    }
    float inv = 1.f / tot;
    for (int i = 0; i < m; i++) tw[i] *= inv;
    return m;
}

__global__ void k_resize_down(const float* __restrict__ in, float* __restrict__ out, float scale) {
    int n = 3 * V1;
    for (int idx = blockIdx.x * blockDim.x + threadIdx.x; idx < n; idx += gridDim.x * blockDim.x) {
        int c = idx / V1; int p = idx % V1;
        int z = p / (H1 * W1); int r = p % (H1 * W1); int y = r / W1; int x = r % W1;
        int zi[4], yi[4], xi[4]; float zw[4], yw[4], xw[4];
        int mz = taps_down(z, D2, zi, zw);
        int my = taps_down(y, H2, yi, yw);
        int mx = taps_down(x, W2, xi, xw);
        const float* ic = in + (size_t)c * V2;
        float a = 0.f;
        for (int iz = 0; iz < mz; iz++)
            for (int iy = 0; iy < my; iy++) {
                float wzy = zw[iz] * yw[iy];
                const float* row = ic + (size_t)zi[iz] * (H2 * W2) + yi[iy] * W2;
                for (int ix = 0; ix < mx; ix++) a += wzy * xw[ix] * row[xi[ix]];
            }
        out[idx] = a * scale;
    }
}

__device__ __forceinline__ void taps_up(int o, int n, int& i0, int& i1, float& w0, float& w1) {
    int j = o >> 1;
    if ((o & 1) == 0) {
        if (j == 0) { i0 = 0; i1 = 0; w0 = 1.f; w1 = 0.f; }
        else        { i0 = j - 1; i1 = j; w0 = 0.25f; w1 = 0.75f; }
    } else {
        if (j + 1 >= n) { i0 = j; i1 = j; w0 = 1.f; w1 = 0.f; }
        else            { i0 = j; i1 = j + 1; w0 = 0.75f; w1 = 0.25f; }
    }
}

__global__ void k_resize_up(const float* __restrict__ in, float* __restrict__ out, int C, float scale) {
    size_t n = (size_t)C * V2;
    for (size_t idx = blockIdx.x * (size_t)blockDim.x + threadIdx.x; idx < n;
         idx += (size_t)gridDim.x * blockDim.x) {
        int c = (int)(idx / V2); int p = (int)(idx % V2);
        int z = p / (H2 * W2); int r = p % (H2 * W2); int y = r / W2; int x = r % W2;
        int z0, z1, y0, y1, x0, x1; float wz0, wz1, wy0, wy1, wx0, wx1;
        taps_up(z, D1, z0, z1, wz0, wz1);
        taps_up(y, H1, y0, y1, wy0, wy1);
        taps_up(x, W1, x0, x1, wx0, wx1);
        const float* ic = in + (size_t)c * V1;
        const int HW = H1 * W1;
        float a =
            wz0 * (wy0 * (wx0 * ic[z0*HW + y0*W1 + x0] + wx1 * ic[z0*HW + y0*W1 + x1]) +
                   wy1 * (wx0 * ic[z0*HW + y1*W1 + x0] + wx1 * ic[z0*HW + y1*W1 + x1])) +
            wz1 * (wy0 * (wx0 * ic[z1*HW + y0*W1 + x0] + wx1 * ic[z1*HW + y0*W1 + x1]) +
                   wy1 * (wx0 * ic[z1*HW + y1*W1 + x0] + wx1 * ic[z1*HW + y1*W1 + x1]));
        out[idx] = a * scale;
    }
}

// ---------------- cost volume (+ leaky 0.05) ----------------
template <int MD>
__global__ void k_costvol(const float* __restrict__ f1, const float* __restrict__ f2,
                          float* __restrict__ out, int C, int D, int H, int W) {
    const int N = 2 * MD + 1;
    size_t V = (size_t)D * H * W;
    const int HW = H * W;
    int i = blockIdx.y;
    float invC = 1.f / (float)C;
    for (size_t p = blockIdx.x * (size_t)blockDim.x + threadIdx.x; p < V;
         p += (size_t)gridDim.x * blockDim.x) {
        int z = (int)(p / HW); int r = (int)(p % HW); int y = r / W; int x = r % W;
        float acc[N * N];
        #pragma unroll
        for (int q = 0; q < N * N; q++) acc[q] = 0.f;
        int zq = z + i - MD;
        if (zq >= 0 && zq < D) {
            for (int c = 0; c < C; c++) {
                float tv = f1[(size_t)c * V + p];
                const float* f2c = f2 + (size_t)c * V + (size_t)zq * HW;
                #pragma unroll
                for (int j = 0; j < N; j++) {
                    int yq = y + j - MD;
                    if (yq < 0 || yq >= H) continue;
                    #pragma unroll
                    for (int k = 0; k < N; k++) {
                        int xq = x + k - MD;
                        if (xq < 0 || xq >= W) continue;
                        acc[j * N + k] += tv * f2c[yq * W + xq];
                    }
                }
            }
        }
        #pragma unroll
        for (int j = 0; j < N; j++)
        #pragma unroll
        for (int k = 0; k < N; k++) {
            float v = acc[j * N + k] * invC;
            v = (v >= 0.f) ? v : 0.05f * v;
            out[(size_t)((i * N + j) * N + k) * V + p] = v;
        }
    }
}

// ---------------- conv3d (3x3x3, SAME) with packed f32x2 FMA ----------------
// Each thread: 4 z-positions x 16 output channels, accumulated as 8 cout-pairs
// in b64 (f32x2) registers. Weight pairs come packed straight from smem (LDS.64,
// uniform broadcast); the input value is duplicated into both lanes once per use.
template <int TX, int TY>
__global__ void __launch_bounds__(TX * TY)
k_conv3d(const float* __restrict__ in, const float* __restrict__ wg,
         const float* __restrict__ bias, float* __restrict__ out,
         int Cin, int Cout, int D, int H, int W, int zTiles, float slope) {
    const int NT = TX * TY;
    const int VZ = 4;
    const int IW = TX + 2, IH = TY + 2, IZ = VZ + 2;
    const int ITILE = IZ * IH * IW;
    __shared__ float s_in[ITILE];
    __shared__ __align__(16) float s_w[27 * 16];

    const int tx = threadIdx.x, ty = threadIdx.y;
    const int tid = ty * TX + tx;
    const int x0 = blockIdx.x * TX, y0 = blockIdx.y * TY;
    const int zt = blockIdx.z % zTiles, ct = blockIdx.z / zTiles;
    const int z0 = zt * VZ;
    const int coutBase = ct * 16;
    const int HW = H * W;
    const size_t V = (size_t)D * HW;

    unsigned long long acc[8 * VZ];   // [pair][vz]
    #pragma unroll
    for (int q = 0; q < 8 * VZ; q++) acc[q] = 0ull;

    for (int ci = 0; ci < Cin; ci++) {
        const float* inc = in + (size_t)ci * V;
        // stage input tile (zero-padded halo)
        for (int l = tid; l < ITILE; l += NT) {
            int zz = l / (IH * IW); int r = l % (IH * IW); int yy = r / IW; int xx = r % IW;
            int gz = z0 - 1 + zz, gy = y0 - 1 + yy, gx = x0 - 1 + xx;
            float v = 0.f;
            if (gz >= 0 && gz < D && gy >= 0 && gy < H && gx >= 0 && gx < W)
                v = inc[(size_t)gz * HW + gy * W + gx];
            s_in[l] = v;
        }
        // stage weights [tap][co]
        for (int l = tid; l < 432; l += NT) {
            int tap = l >> 4, co = l & 15;
            int cog = coutBase + co;
            s_w[l] = (cog < Cout) ? wg[((size_t)cog * Cin + ci) * 27 + tap] : 0.f;
        }
        __syncthreads();

        #pragma unroll
        for (int ky = 0; ky < 3; ky++)
        #pragma unroll
        for (int kx = 0; kx < 3; kx++) {
            // 6-deep z window for this (ky,kx) column
            unsigned long long ivp[6];
            #pragma unroll
            for (int zz = 0; zz < 6; zz++)
                ivp[zz] = dup_f32x2(s_in[zz * IH * IW + (ty + ky) * IW + (tx + kx)]);
            #pragma unroll
            for (int kz = 0; kz < 3; kz++) {
                const unsigned long long* wp =
                    reinterpret_cast<const unsigned long long*>(s_w + (kz * 9 + ky * 3 + kx) * 16);
                #pragma unroll
                for (int p = 0; p < 8; p++) {
                    unsigned long long w2 = wp[p];
                    #pragma unroll
                    for (int vz = 0; vz < VZ; vz++)
                        fma_f32x2(acc[p * VZ + vz], ivp[kz + vz], w2);
                }
            }
        }
        __syncthreads();
    }

    const int gx = x0 + tx, gy = y0 + ty;
    if (gx < W && gy < H) {
        #pragma unroll
        for (int p = 0; p < 8; p++) {
            int c0 = coutBase + 2 * p, c1 = c0 + 1;
            float b0 = (c0 < Cout) ? bias[c0] : 0.f;
            float b1 = (c1 < Cout) ? bias[c1] : 0.f;
            #pragma unroll
            for (int vz = 0; vz < VZ; vz++) {
                int gz = z0 + vz;
                if (gz >= D) continue;
                float v0, v1;
                unpack_f32x2(acc[p * VZ + vz], v0, v1);
                size_t sp = (size_t)gz * HW + (size_t)gy * W + gx;
                if (c0 < Cout) {
                    float v = v0 + b0; v = (v >= 0.f) ? v : v * slope;
                    out[(size_t)c0 * V + sp] = v;
                }
                if (c1 < Cout) {
                    float v = v1 + b1; v = (v >= 0.f) ? v : v * slope;
                    out[(size_t)c1 * V + sp] = v;
                }
            }
        }
    }
}

// ---------------- host-side launch helpers ----------------
static void launch_conv_coarse(const float* in, const float* w, const float* b, float* out,
                               int Cin, int Cout, float slope) {
    dim3 blk(16, 8);
    int zT = D1 / 4;                         // 12
    dim3 grd(W1 / 16, H1 / 8, zT * ((Cout + 15) / 16));
    k_conv3d<16, 8><<<grd, blk>>>(in, w, b, out, Cin, Cout, D1, H1, W1, zT, slope);
}

static void launch_conv_fine(const float* in, const float* w, const float* b, float* out,
                             int Cin, int Cout, float slope) {
    dim3 blk(32, 8);
    int zT = D2 / 4;                         // 24
    dim3 grd(W2 / 32, H2 / 8, zT * ((Cout + 15) / 16));
    k_conv3d<32, 8><<<grd, blk>>>(in, w, b, out, Cin, Cout, D2, H2, W2, zT, slope);
}

extern "C" void kernel_launch(void* const* d_in, const int* in_sizes, int n_in,
                              void* d_out, int out_size) {
    const float* t_ptr  = (const float*)d_in[0];
    const float* dispup = (const float*)d_in[1];
    const float* fx     = (const float*)d_in[2];
    const float* fy     = (const float*)d_in[3];
    const float* fxu    = (const float*)d_in[4];
    const float* fyu    = (const float*)d_in[5];
    const float* ctx    = (const float*)d_in[6];
    const float* w1_[5] = {(const float*)d_in[7],  (const float*)d_in[9],
                           (const float*)d_in[11], (const float*)d_in[13],
                           (const float*)d_in[15]};
    const float* b1_[5] = {(const float*)d_in[8],  (const float*)d_in[10],
                           (const float*)d_in[12], (const float*)d_in[14],
                           (const float*)d_in[16]};
    const float* w2_[3] = {(const float*)d_in[17], (const float*)d_in[19],
                           (const float*)d_in[21]};
    const float* b2_[3] = {(const float*)d_in[18], (const float*)d_in[20],
                           (const float*)d_in[22]};

    float* A = nullptr;
    cudaGetSymbolAddress((void**)&A, g_arena);

    float* xin1   = A + O_XIN1;
    float* xin2   = A + O_XIN2;
    float* ctx16  = A + O_CTX;
    float* vel    = A + O_VEL;
    float* velup  = A + O_VELUP;
    float* xout2  = A + O_XOUT2;
    float* velup2 = A + O_VELUP2;
    float* wn1    = A + O_WN1;
    float* tn1    = A + O_TN1;
    float* wn2    = A + O_WN2;
    float* tn2    = A + O_TN2;

    float* cv1    = xin1;
    float* fyc    = xin1 + 125ull * V1;
    float* wx     = xin1 + 157ull * V1;
    float* ctxc   = xin1 + 189ull * V1;
    float* disp   = xin1 + 221ull * V1;

    float* cv2    = xin2;
    float* fyuc   = xin2 + 27ull * V2;
    float* wxu    = xin2 + 43ull * V2;
    float* upctx  = xin2 + 59ull * V2;
    float* disp2  = xin2 + 75ull * V2;

    float* outf = (float*)d_out;

    const int TPB = 256;
    const int GB1 = (V1 + TPB - 1) / TPB;          // 360
    const int GB2 = (V2 + TPB - 1) / TPB;          // 2880

    cudaMemsetAsync(d_out, 0, (size_t)out_size * sizeof(float), 0);

    // ---- coarse stage ----
    k_resize_down<<<(3 * V1 + TPB - 1) / TPB, TPB>>>(dispup, disp, 0.5f);
    k_warp<<<GB1, TPB>>>(fx, disp, wx, 32, D1, H1, W1, 0);
    cudaMemcpyAsync(fyc,  fy,  32ull * V1 * sizeof(float), cudaMemcpyDeviceToDevice, 0);
    cudaMemcpyAsync(ctxc, ctx, 32ull * V1 * sizeof(float), cudaMemcpyDeviceToDevice, 0);
    k_zero_red<<<1, 4>>>();
    k_reduce<<<512, 256>>>(wx, 32 * V1, 0);
    k_reduce<<<512, 256>>>(fy, 32 * V1, 2);
    k_finalize_ms<<<1, 1>>>((double)(32 * V1));
    k_normalize<<<(32 * V1 + TPB - 1) / TPB, TPB>>>(wx, wn1, 32 * V1);
    k_normalize<<<(32 * V1 + TPB - 1) / TPB, TPB>>>(fy, tn1, 32 * V1);
    k_costvol<2><<<dim3(GB1, 5), TPB>>>(tn1, wn1, cv1, 32, D1, H1, W1);
    launch_conv_coarse(xin1, w1_[0], b1_[0], xin1 + 224ull * V1, 224, 64, 0.02f);
    launch_conv_coarse(xin1, w1_[1], b1_[1], xin1 + 288ull * V1, 288, 48, 0.02f);
    launch_conv_coarse(xin1, w1_[2], b1_[2], xin1 + 336ull * V1, 336, 32, 0.02f);
    launch_conv_coarse(xin1, w1_[3], b1_[3], ctx16,              368, 16, 0.02f);
    launch_conv_coarse(ctx16, w1_[4], b1_[4], vel,                16,  3, 1.0f);

    // ---- upsample + fine stage ----
    k_resize_up<<<GB2 * 2, TPB>>>(ctx16, upctx, 16, 1.0f);
    k_resize_up<<<GB2, TPB>>>(vel, velup, 3, 2.0f);
    k_warp<<<GB2, TPB>>>(dispup, velup, disp2, 3, D2, H2, W2, 1);
    k_warp<<<GB2, TPB>>>(fxu, disp2, wxu, 16, D2, H2, W2, 0);
    cudaMemcpyAsync(fyuc, fyu, 16ull * V2 * sizeof(float), cudaMemcpyDeviceToDevice, 0);
    k_zero_red<<<1, 4>>>();
    k_reduce<<<1024, 256>>>(wxu, 16 * V2, 0);
    k_reduce<<<1024, 256>>>(fyu, 16 * V2, 2);
    k_finalize_ms<<<1, 1>>>((double)(16 * V2));
    k_normalize<<<(16 * V2 + TPB - 1) / TPB, TPB>>>(wxu, wn2, 16 * V2);
    k_normalize<<<(16 * V2 + TPB - 1) / TPB, TPB>>>(fyu, tn2, 16 * V2);
    k_costvol<1><<<dim3(GB2, 3), TPB>>>(tn2, wn2, cv2, 16, D2, H2, W2);
    launch_conv_fine(xin2, w2_[0], b2_[0], xin2 + 78ull * V2, 78, 32, 0.02f);
    launch_conv_fine(xin2, w2_[1], b2_[1], xout2,            110, 16, 0.02f);
    launch_conv_fine(xout2, w2_[2], b2_[2], velup2,           16,  3, 1.0f);

    k_final<<<GB2, TPB>>>(disp2, velup2, dispup, t_ptr, outf);
}